// round 1
// baseline (speedup 1.0000x reference)
#include <cuda_runtime.h>
#include <math.h>

#define T_N  4096
#define EMB  384
#define HID  256
#define NH   4
#define HD   64
#define MD   32
#define S0   33          // 1 + MD
#define NS   4063        // T_N - 1 - MD

// ---------------- scratch (device globals: no allocation allowed) ----------------
__device__ float g_h  [T_N * HID];
__device__ float g_x  [T_N * HID];
__device__ float g_Wh [T_N * HID];
__device__ float g_hn [T_N * HID];
__device__ float g_src[NH * T_N];
__device__ float g_dst[NH * T_N];
__device__ float g_dmax[NH];
__device__ float g_scal[4];
__device__ float g_scores[NS];
__device__ float g_cosf[NS];
__device__ float g_aw[NS];

// ---------------- reduction helpers ----------------
__device__ __forceinline__ float warpSum(float v) {
    #pragma unroll
    for (int o = 16; o; o >>= 1) v += __shfl_xor_sync(0xffffffffu, v, o);
    return v;
}
__device__ __forceinline__ float warpMax(float v) {
    #pragma unroll
    for (int o = 16; o; o >>= 1) v = fmaxf(v, __shfl_xor_sync(0xffffffffu, v, o));
    return v;
}

// block-wide sum for 256 threads; result valid in all threads
__device__ float blockSum256(float v) {
    __shared__ float sh[8];
    int w = threadIdx.x >> 5, l = threadIdx.x & 31;
    v = warpSum(v);
    if (l == 0) sh[w] = v;
    __syncthreads();
    float s = (threadIdx.x < 8) ? sh[threadIdx.x] : 0.f;
    if (w == 0) {
        s = warpSum(s);
        if (l == 0) sh[0] = s;
    }
    __syncthreads();
    float r = sh[0];
    __syncthreads();
    return r;
}

// ---------------- generic 16-row GEMM:  C[r0:r0+16, 0:256] = A[16,K] @ Wt[256,K]^T ----------------
#define GEMM_STEP(WV, KK)                                                     \
    {                                                                         \
        const float4* av = (const float4*)&sa[(KK) * 16];                     \
        float4 a0 = av[0], a1 = av[1], a2 = av[2], a3 = av[3];                \
        acc[0]  += a0.x * (WV); acc[1]  += a0.y * (WV);                       \
        acc[2]  += a0.z * (WV); acc[3]  += a0.w * (WV);                       \
        acc[4]  += a1.x * (WV); acc[5]  += a1.y * (WV);                       \
        acc[6]  += a1.z * (WV); acc[7]  += a1.w * (WV);                       \
        acc[8]  += a2.x * (WV); acc[9]  += a2.y * (WV);                       \
        acc[10] += a2.z * (WV); acc[11] += a2.w * (WV);                       \
        acc[12] += a3.x * (WV); acc[13] += a3.y * (WV);                       \
        acc[14] += a3.z * (WV); acc[15] += a3.w * (WV);                       \
    }

__global__ void __launch_bounds__(256) gemm16(const float* __restrict__ A,
                                              const float* __restrict__ Wt,
                                              const float* __restrict__ bias,
                                              float* __restrict__ Cout,
                                              int K, int doRelu)
{
    __shared__ float sa[EMB * 16];  // max K = 384
    int r0 = blockIdx.x * 16;
    for (int idx = threadIdx.x; idx < 16 * K; idx += 256) {
        int r = idx / K, k = idx - r * K;
        sa[k * 16 + r] = A[(size_t)(r0 + r) * K + k];
    }
    __syncthreads();
    float acc[16];
    #pragma unroll
    for (int r = 0; r < 16; r++) acc[r] = 0.f;
    int c = threadIdx.x;
    const float4* w4 = (const float4*)(Wt + (size_t)c * K);
    int K4 = K >> 2;
    for (int k4 = 0; k4 < K4; k4++) {
        float4 w = w4[k4];
        int kb = k4 * 4;
        GEMM_STEP(w.x, kb + 0)
        GEMM_STEP(w.y, kb + 1)
        GEMM_STEP(w.z, kb + 2)
        GEMM_STEP(w.w, kb + 3)
    }
    float b = bias ? bias[c] : 0.f;
    #pragma unroll
    for (int r = 0; r < 16; r++) {
        float v = acc[r] + b;
        if (doRelu) v = fmaxf(v, 0.f);
        Cout[(size_t)(r0 + r) * HID + c] = v;
    }
}

// ---------------- inv-norm of row 0 of g_h -> g_scal[slot] ----------------
__global__ void __launch_bounds__(256) rownorm0(int slot)
{
    float v = g_h[threadIdx.x];
    float s = blockSum256(v * v);
    if (threadIdx.x == 0) g_scal[slot] = 1.f / (sqrtf(s) + 1e-8f);
}

// ---------------- query-aware cosine update of sentence rows ----------------
__global__ void __launch_bounds__(256) cos_update()
{
    __shared__ float q[HID];
    int tid = threadIdx.x;
    q[tid] = g_h[tid];
    __syncthreads();
    int w = tid >> 5, l = tid & 31;
    int j = blockIdx.x * 8 + w;
    if (j >= NS) return;
    float* s = &g_h[(size_t)(S0 + j) * HID];
    float sv[8];
    float qs = 0.f, ss = 0.f;
    #pragma unroll
    for (int e = 0; e < 8; e++) {
        float x = s[l + 32 * e];
        sv[e] = x;
        qs += q[l + 32 * e] * x;
        ss += x * x;
    }
    qs = warpSum(qs);
    ss = warpSum(ss);
    float cs = qs * g_scal[0] / (sqrtf(ss) + 1e-8f);
    #pragma unroll
    for (int e = 0; e < 8; e++)
        s[l + 32 * e] = sv[e] + 0.8f * q[l + 32 * e] * cs;
}

// ---------------- layernorm: g_x = LN(g_h) * scale + bias ----------------
__global__ void __launch_bounds__(256) ln_k(const float* __restrict__ scale,
                                            const float* __restrict__ bias)
{
    int row = blockIdx.x, tid = threadIdx.x;
    float v = g_h[(size_t)row * HID + tid];
    float mu = blockSum256(v) * (1.f / HID);
    float d = v - mu;
    float var = blockSum256(d * d) * (1.f / HID);
    g_x[(size_t)row * HID + tid] = d * rsqrtf(var + 1e-5f) * scale[tid] + bias[tid];
}

// ---------------- src/dst projections:  src[h,n] = Wh[n, h*64: ] . a[h,:64] ----------------
__global__ void __launch_bounds__(256) srcdst_k(const float* __restrict__ ga)
{
    int w = threadIdx.x >> 5, l = threadIdx.x & 31;
    int gid = blockIdx.x * 8 + w;
    int n = gid >> 2, hh = gid & 3;
    const float* wp = &g_Wh[(size_t)n * HID + hh * HD];
    float v0 = wp[l], v1 = wp[l + 32];
    const float* a = ga + hh * 2 * HD;
    float s = v0 * a[l] + v1 * a[l + 32];
    float d = v0 * a[HD + l] + v1 * a[HD + l + 32];
    s = warpSum(s);
    d = warpSum(d);
    if (l == 0) { g_src[hh * T_N + n] = s; g_dst[hh * T_N + n] = d; }
}

// ---------------- per-head max of dst (softmax bound) ----------------
__global__ void __launch_bounds__(256) dmax_k()
{
    int h = blockIdx.x;
    float m = -1e30f;
    for (int i = threadIdx.x; i < T_N; i += 256) m = fmaxf(m, g_dst[h * T_N + i]);
    __shared__ float sh[8];
    int w = threadIdx.x >> 5, l = threadIdx.x & 31;
    m = warpMax(m);
    if (l == 0) sh[w] = m;
    __syncthreads();
    if (threadIdx.x == 0) {
        float mm = sh[0];
        #pragma unroll
        for (int i = 1; i < 8; i++) mm = fmaxf(mm, sh[i]);
        g_dmax[h] = mm;
    }
}

// ---------------- fused masked-softmax attention + P@Wh ----------------
// CTA: 256 threads, 16 rows.  Phase A: 64 (r,h) producer groups build the weight
// tile (exp of leaky-relu, masked) into smem.  Phase B: thread t owns output
// column t (head t/64), accumulating 16 rows as 8 packed f32x2 accumulators via
// fma.rn.f32x2 (2x scalar FFMA throughput).
__global__ void __launch_bounds__(256) attn_k(const int* __restrict__ adj)
{
    __shared__ __align__(16) float w_s[NH][32][20];   // [head][j_local][row(+pad)]
    __shared__ float srcb[16][NH], msub[16][NH];
    __shared__ float zp[64][4], zfin[16][NH];

    int tid = threadIdx.x;
    int row0 = blockIdx.x * 16;

    if (tid < 64) {
        int r = tid >> 2, hh = tid & 3;
        float s = g_src[hh * T_N + row0 + r];
        srcb[r][hh] = s;
        float m = s + g_dmax[hh];
        msub[r][hh] = (m > 0.f) ? m : 0.2f * m;   // lrelu of upper bound >= all e_ij
    }
    __syncthreads();

    // phase-A thread constants: 4 threads per (row, head), 8 j's each
    int p = tid >> 2, quarter = tid & 3;
    int ar = p >> 2, ah = p & 3;
    float asrc = srcb[ar][ah], amsub = msub[ar][ah];
    const int* adjrow = adj + (size_t)(row0 + ar) * T_N;
    const float* dsth = &g_dst[ah * T_N];

    // phase-B thread constants
    int h = tid >> 6, col = tid;

    unsigned long long acc2[8];
    #pragma unroll
    for (int i = 0; i < 8; i++) acc2[i] = 0ull;
    float zpart = 0.f;

    for (int j0 = 0; j0 < T_N; j0 += 32) {
        // ---- phase A: produce masked exp weights for this j-tile ----
        #pragma unroll
        for (int e = 0; e < 8; e++) {
            int jl = quarter * 8 + e;
            int j = j0 + jl;
            int av = adjrow[j];
            float ev = asrc + dsth[j];
            ev = (ev > 0.f) ? ev : 0.2f * ev;
            float wv = av ? __expf(ev - amsub) : 0.f;
            w_s[ah][jl][ar] = wv;
            zpart += wv;
        }
        __syncthreads();

        // ---- phase B: acc[r] += w[r][h][j] * Wh[j, col], rows packed in pairs ----
        const float* whp = &g_Wh[(size_t)j0 * HID + col];
        #pragma unroll
        for (int jl = 0; jl < 32; jl++) {
            float whv = whp[jl * HID];
            unsigned long long wh2;
            asm("mov.b64 %0, {%1, %1};" : "=l"(wh2) : "r"(__float_as_uint(whv)));
            const unsigned long long* wp =
                (const unsigned long long*)&w_s[h][jl][0];
            #pragma unroll
            for (int rp = 0; rp < 8; rp++) {
                asm("fma.rn.f32x2 %0, %1, %2, %0;"
                    : "+l"(acc2[rp]) : "l"(wp[rp]), "l"(wh2));
            }
        }
        __syncthreads();
    }

    // ---- reduce Z (4 partials per (r,h)) ----
    zp[p][quarter] = zpart;
    __syncthreads();
    if (tid < 64)
        zfin[tid >> 2][tid & 3] = zp[tid][0] + zp[tid][1] + zp[tid][2] + zp[tid][3];
    __syncthreads();

    #pragma unroll
    for (int rp = 0; rp < 8; rp++) {
        float lo = __uint_as_float((unsigned)(acc2[rp] & 0xffffffffull));
        float hi = __uint_as_float((unsigned)(acc2[rp] >> 32));
        g_hn[(size_t)(row0 + 2 * rp)     * HID + col] = lo / zfin[2 * rp][h];
        g_hn[(size_t)(row0 + 2 * rp + 1) * HID + col] = hi / zfin[2 * rp + 1][h];
    }
}

// ---------------- residual combine: h = 0.5*relu(hn) + 0.5*h ----------------
__global__ void __launch_bounds__(256) combine_k()
{
    size_t i = (size_t)blockIdx.x * 256 + threadIdx.x;
    float hv = g_h[i], nv = g_hn[i];
    g_h[i] = 0.5f * fmaxf(nv, 0.f) + 0.5f * hv;
}

// ---------------- final scores + cosf ----------------
__global__ void __launch_bounds__(256) scorecos_k()
{
    __shared__ float q[HID];
    int tid = threadIdx.x;
    q[tid] = g_h[tid];
    __syncthreads();
    int w = tid >> 5, l = tid & 31;
    int j = blockIdx.x * 8 + w;
    if (j >= NS) return;
    const float* s = &g_h[(size_t)(S0 + j) * HID];
    float qs = 0.f, ss = 0.f;
    #pragma unroll
    for (int e = 0; e < 8; e++) {
        float x = s[l + 32 * e];
        qs += q[l + 32 * e] * x;
        ss += x * x;
    }
    qs = warpSum(qs);
    ss = warpSum(ss);
    if (l == 0) {
        g_scores[j] = qs * (1.0f / 16.0f);
        g_cosf[j] = qs * g_scal[1] / (sqrtf(ss) + 1e-8f);
    }
}

// ---------------- softmax over the 4063 scores (one CTA) ----------------
__global__ void __launch_bounds__(1024) softmax_k()
{
    __shared__ float sh[32];
    int tid = threadIdx.x, w = tid >> 5, l = tid & 31;

    float m = -1e30f;
    for (int i = tid; i < NS; i += 1024) m = fmaxf(m, g_scores[i]);
    m = warpMax(m);
    if (l == 0) sh[w] = m;
    __syncthreads();
    if (w == 0) {
        float mm = sh[l];
        mm = warpMax(mm);
        if (l == 0) sh[0] = mm;
    }
    __syncthreads();
    m = sh[0];
    __syncthreads();

    float sum = 0.f;
    for (int i = tid; i < NS; i += 1024) {
        float e = __expf(g_scores[i] - m);
        g_aw[i] = e;
        sum += e;
    }
    sum = warpSum(sum);
    if (l == 0) sh[w] = sum;
    __syncthreads();
    if (w == 0) {
        float ss = sh[l];
        ss = warpSum(ss);
        if (l == 0) sh[0] = ss;
    }
    __syncthreads();
    float inv = 1.f / sh[0];
    for (int i = tid; i < NS; i += 1024) g_aw[i] *= inv;
}

// ---------------- fusion MLP + output head ----------------
__global__ void __launch_bounds__(256) fusion_k(const float* __restrict__ fw,
                                                const float* __restrict__ fb,
                                                const float* __restrict__ ow,
                                                const float* __restrict__ obp,
                                                float* __restrict__ out)
{
    __shared__ float feat[514][16];   // [k][row]  (row-vectorized)
    __shared__ float awv[16], cosv[16];
    __shared__ float red2[16][8];
    int tid = threadIdx.x;
    int j0 = blockIdx.x * 16;

    if (tid < 16) {
        int j = j0 + tid;
        awv[tid]  = (j < NS) ? g_aw[j]   : 0.f;
        cosv[tid] = (j < NS) ? g_cosf[j] : 0.f;
    }
    __syncthreads();

    for (int idx = tid; idx < 16 * 514; idx += 256) {
        int r = idx / 514, k = idx - r * 514;
        int j = j0 + r;
        float v = 0.f;
        if (j < NS) {
            if (k < 256)      v = g_h[(size_t)(S0 + j) * HID + k];
            else if (k < 512) v = g_h[k - 256] * (awv[r] + 0.5f);
            else if (k == 512) v = cosv[r];
            else              v = awv[r];
        }
        feat[k][r] = v;
    }
    __syncthreads();

    int c = tid;
    float acc[16];
    #pragma unroll
    for (int r = 0; r < 16; r++) acc[r] = 0.f;
    const float* wrow = fw + (size_t)c * 514;
    for (int k = 0; k < 514; k++) {
        float wv = wrow[k];
        const float4* av = (const float4*)&feat[k][0];
        float4 a0 = av[0], a1 = av[1], a2 = av[2], a3 = av[3];
        acc[0]  += a0.x * wv; acc[1]  += a0.y * wv;
        acc[2]  += a0.z * wv; acc[3]  += a0.w * wv;
        acc[4]  += a1.x * wv; acc[5]  += a1.y * wv;
        acc[6]  += a1.z * wv; acc[7]  += a1.w * wv;
        acc[8]  += a2.x * wv; acc[9]  += a2.y * wv;
        acc[10] += a2.z * wv; acc[11] += a2.w * wv;
        acc[12] += a3.x * wv; acc[13] += a3.y * wv;
        acc[14] += a3.z * wv; acc[15] += a3.w * wv;
    }
    float fbv = fb[c];
    float owv = ow[c];
    int w = tid >> 5, l = tid & 31;
    #pragma unroll
    for (int r = 0; r < 16; r++) {
        float gv = fmaxf(acc[r] + fbv, 0.f) * owv;
        gv = warpSum(gv);
        if (l == 0) red2[r][w] = gv;
    }
    __syncthreads();
    if (tid < 16) {
        float s = 0.f;
        #pragma unroll
        for (int ww = 0; ww < 8; ww++) s += red2[tid][ww];
        int j = j0 + tid;
        if (j < NS) out[j] = s + obp[0] + 0.5f * cosv[tid];
    }
}

// ---------------- launch ----------------
extern "C" void kernel_launch(void* const* d_in, const int* in_sizes, int n_in,
                              void* d_out, int out_size)
{
    const float* emb    = (const float*)d_in[0];
    const int*   adj    = (const int*)  d_in[1];
    const float* proj_w = (const float*)d_in[3];
    const float* proj_b = (const float*)d_in[4];
    const float* ln_s   = (const float*)d_in[5];
    const float* ln_b   = (const float*)d_in[6];
    const float* gat_W  = (const float*)d_in[7];
    const float* gat_a  = (const float*)d_in[8];
    const float* fw     = (const float*)d_in[9];
    const float* fb     = (const float*)d_in[10];
    const float* ow     = (const float*)d_in[11];
    const float* ob     = (const float*)d_in[12];
    float* out = (float*)d_out;

    float *hP, *xP, *whP;
    cudaGetSymbolAddress((void**)&hP,  g_h);
    cudaGetSymbolAddress((void**)&xP,  g_x);
    cudaGetSymbolAddress((void**)&whP, g_Wh);

    // h = relu(E @ proj_w^T + b)
    gemm16<<<T_N / 16, 256>>>(emb, proj_w, proj_b, hP, EMB, 1);
    // query-aware cosine update of sentence rows
    rownorm0<<<1, 256>>>(0);
    cos_update<<<(NS + 7) / 8, 256>>>();

    for (int L = 0; L < 2; L++) {
        ln_k<<<T_N, 256>>>(ln_s + L * HID, ln_b + L * HID);
        gemm16<<<T_N / 16, 256>>>(xP, gat_W + (size_t)L * HID * HID, nullptr, whP, HID, 0);
        srcdst_k<<<T_N * NH / 8, 256>>>(gat_a + L * NH * 2 * HD);
        dmax_k<<<NH, 256>>>();
        attn_k<<<T_N / 16, 256>>>(adj);
        combine_k<<<T_N * HID / 256, 256>>>();
    }

    rownorm0<<<1, 256>>>(1);
    scorecos_k<<<(NS + 7) / 8, 256>>>();
    softmax_k<<<1, 1024>>>();
    fusion_k<<<(NS + 15) / 16, 256>>>(fw, fb, ow, ob, out);
}

// round 2
// speedup vs baseline: 1.0507x; 1.0507x over previous
#include <cuda_runtime.h>
#include <math.h>

#define T_N  4096
#define EMB  384
#define HID  256
#define NH   4
#define HD   64
#define MD   32
#define S0   33          // 1 + MD
#define NS   4063        // T_N - 1 - MD

// ---------------- scratch (device globals: no allocation allowed) ----------------
__device__ float g_h  [T_N * HID];
__device__ float g_x  [T_N * HID];
__device__ float g_Wh [T_N * HID];
__device__ float g_hn [T_N * HID];
__device__ float g_src[NH * T_N];
__device__ float g_dst[NH * T_N];
__device__ float g_dmax[NH];
__device__ float g_scal[4];
__device__ float g_scores[NS];
__device__ float g_cosf[NS];
__device__ float g_aw[NS];

// ---------------- reduction helpers ----------------
__device__ __forceinline__ float warpSum(float v) {
    #pragma unroll
    for (int o = 16; o; o >>= 1) v += __shfl_xor_sync(0xffffffffu, v, o);
    return v;
}
__device__ __forceinline__ float warpMax(float v) {
    #pragma unroll
    for (int o = 16; o; o >>= 1) v = fmaxf(v, __shfl_xor_sync(0xffffffffu, v, o));
    return v;
}

// block-wide sum for 256 threads; result valid in all threads
__device__ float blockSum256(float v) {
    __shared__ float sh[8];
    int w = threadIdx.x >> 5, l = threadIdx.x & 31;
    v = warpSum(v);
    if (l == 0) sh[w] = v;
    __syncthreads();
    float s = (threadIdx.x < 8) ? sh[threadIdx.x] : 0.f;
    if (w == 0) {
        s = warpSum(s);
        if (l == 0) sh[0] = s;
    }
    __syncthreads();
    float r = sh[0];
    __syncthreads();
    return r;
}

// ---------------- generic 16-row GEMM:  C[r0:r0+16, 0:256] = A[16,K] @ Wt[256,K]^T ----------------
#define GEMM_STEP(WV, KK)                                                     \
    {                                                                         \
        const float4* av = (const float4*)&sa[(KK) * 16];                     \
        float4 a0 = av[0], a1 = av[1], a2 = av[2], a3 = av[3];                \
        acc[0]  += a0.x * (WV); acc[1]  += a0.y * (WV);                       \
        acc[2]  += a0.z * (WV); acc[3]  += a0.w * (WV);                       \
        acc[4]  += a1.x * (WV); acc[5]  += a1.y * (WV);                       \
        acc[6]  += a1.z * (WV); acc[7]  += a1.w * (WV);                       \
        acc[8]  += a2.x * (WV); acc[9]  += a2.y * (WV);                       \
        acc[10] += a2.z * (WV); acc[11] += a2.w * (WV);                       \
        acc[12] += a3.x * (WV); acc[13] += a3.y * (WV);                       \
        acc[14] += a3.z * (WV); acc[15] += a3.w * (WV);                       \
    }

__global__ void __launch_bounds__(256) gemm16(const float* __restrict__ A,
                                              const float* __restrict__ Wt,
                                              const float* __restrict__ bias,
                                              float* __restrict__ Cout,
                                              int K, int doRelu)
{
    __shared__ float sa[EMB * 16];  // max K = 384
    int r0 = blockIdx.x * 16;
    for (int idx = threadIdx.x; idx < 16 * K; idx += 256) {
        int r = idx / K, k = idx - r * K;
        sa[k * 16 + r] = A[(size_t)(r0 + r) * K + k];
    }
    __syncthreads();
    float acc[16];
    #pragma unroll
    for (int r = 0; r < 16; r++) acc[r] = 0.f;
    int c = threadIdx.x;
    const float4* w4 = (const float4*)(Wt + (size_t)c * K);
    int K4 = K >> 2;
    for (int k4 = 0; k4 < K4; k4++) {
        float4 w = w4[k4];
        int kb = k4 * 4;
        GEMM_STEP(w.x, kb + 0)
        GEMM_STEP(w.y, kb + 1)
        GEMM_STEP(w.z, kb + 2)
        GEMM_STEP(w.w, kb + 3)
    }
    float b = bias ? bias[c] : 0.f;
    #pragma unroll
    for (int r = 0; r < 16; r++) {
        float v = acc[r] + b;
        if (doRelu) v = fmaxf(v, 0.f);
        Cout[(size_t)(r0 + r) * HID + c] = v;
    }
}

// ---------------- inv-norm of row 0 of g_h -> g_scal[slot] ----------------
__global__ void __launch_bounds__(256) rownorm0(int slot)
{
    float v = g_h[threadIdx.x];
    float s = blockSum256(v * v);
    if (threadIdx.x == 0) g_scal[slot] = 1.f / (sqrtf(s) + 1e-8f);
}

// ---------------- query-aware cosine update of sentence rows ----------------
__global__ void __launch_bounds__(256) cos_update()
{
    __shared__ float q[HID];
    int tid = threadIdx.x;
    q[tid] = g_h[tid];
    __syncthreads();
    int w = tid >> 5, l = tid & 31;
    int j = blockIdx.x * 8 + w;
    if (j >= NS) return;
    float* s = &g_h[(size_t)(S0 + j) * HID];
    float sv[8];
    float qs = 0.f, ss = 0.f;
    #pragma unroll
    for (int e = 0; e < 8; e++) {
        float x = s[l + 32 * e];
        sv[e] = x;
        qs += q[l + 32 * e] * x;
        ss += x * x;
    }
    qs = warpSum(qs);
    ss = warpSum(ss);
    float cs = qs * g_scal[0] / (sqrtf(ss) + 1e-8f);
    #pragma unroll
    for (int e = 0; e < 8; e++)
        s[l + 32 * e] = sv[e] + 0.8f * q[l + 32 * e] * cs;
}

// ---------------- layernorm: g_x = LN(g_h) * scale + bias ----------------
__global__ void __launch_bounds__(256) ln_k(const float* __restrict__ scale,
                                            const float* __restrict__ bias)
{
    int row = blockIdx.x, tid = threadIdx.x;
    float v = g_h[(size_t)row * HID + tid];
    float mu = blockSum256(v) * (1.f / HID);
    float d = v - mu;
    float var = blockSum256(d * d) * (1.f / HID);
    g_x[(size_t)row * HID + tid] = d * rsqrtf(var + 1e-5f) * scale[tid] + bias[tid];
}

// ---------------- src/dst projections:  src[h,n] = Wh[n, h*64: ] . a[h,:64] ----------------
__global__ void __launch_bounds__(256) srcdst_k(const float* __restrict__ ga)
{
    int w = threadIdx.x >> 5, l = threadIdx.x & 31;
    int gid = blockIdx.x * 8 + w;
    int n = gid >> 2, hh = gid & 3;
    const float* wp = &g_Wh[(size_t)n * HID + hh * HD];
    float v0 = wp[l], v1 = wp[l + 32];
    const float* a = ga + hh * 2 * HD;
    float s = v0 * a[l] + v1 * a[l + 32];
    float d = v0 * a[HD + l] + v1 * a[HD + l + 32];
    s = warpSum(s);
    d = warpSum(d);
    if (l == 0) { g_src[hh * T_N + n] = s; g_dst[hh * T_N + n] = d; }
}

// ---------------- per-head max of dst (softmax bound) ----------------
__global__ void __launch_bounds__(256) dmax_k()
{
    int h = blockIdx.x;
    float m = -1e30f;
    for (int i = threadIdx.x; i < T_N; i += 256) m = fmaxf(m, g_dst[h * T_N + i]);
    __shared__ float sh[8];
    int w = threadIdx.x >> 5, l = threadIdx.x & 31;
    m = warpMax(m);
    if (l == 0) sh[w] = m;
    __syncthreads();
    if (threadIdx.x == 0) {
        float mm = sh[0];
        #pragma unroll
        for (int i = 1; i < 8; i++) mm = fmaxf(mm, sh[i]);
        g_dmax[h] = mm;
    }
}

// ---------------- fused masked-softmax attention + P@Wh ----------------
// CTA: 256 threads, 16 rows.  Phase A: 64 (r,h) producer groups build the weight
// tile (exp of leaky-relu, masked) into smem.  Phase B: thread t owns output
// column t (head t/64), accumulating 16 rows as 8 packed f32x2 accumulators via
// fma.rn.f32x2 (2x scalar FFMA throughput).
__global__ void __launch_bounds__(256) attn_k(const int* __restrict__ adj)
{
    __shared__ __align__(16) float w_s[NH][32][20];   // [head][j_local][row(+pad)]
    __shared__ float srcb[16][NH], msub[16][NH];
    __shared__ float zp[64][4], zfin[16][NH];

    int tid = threadIdx.x;
    int row0 = blockIdx.x * 16;

    if (tid < 64) {
        int r = tid >> 2, hh = tid & 3;
        float s = g_src[hh * T_N + row0 + r];
        srcb[r][hh] = s;
        float m = s + g_dmax[hh];
        msub[r][hh] = (m > 0.f) ? m : 0.2f * m;   // lrelu of upper bound >= all e_ij
    }
    __syncthreads();

    // phase-A thread constants: 4 threads per (row, head), 8 j's each
    int p = tid >> 2, quarter = tid & 3;
    int ar = p >> 2, ah = p & 3;
    float asrc = srcb[ar][ah], amsub = msub[ar][ah];
    const int* adjrow = adj + (size_t)(row0 + ar) * T_N;
    const float* dsth = &g_dst[ah * T_N];

    // phase-B thread constants
    int h = tid >> 6, col = tid;

    unsigned long long acc2[8];
    #pragma unroll
    for (int i = 0; i < 8; i++) acc2[i] = 0ull;
    float zpart = 0.f;

    for (int j0 = 0; j0 < T_N; j0 += 32) {
        // ---- phase A: produce masked exp weights for this j-tile ----
        #pragma unroll
        for (int e = 0; e < 8; e++) {
            int jl = quarter * 8 + e;
            int j = j0 + jl;
            int av = adjrow[j];
            float ev = asrc + dsth[j];
            ev = (ev > 0.f) ? ev : 0.2f * ev;
            float wv = av ? __expf(ev - amsub) : 0.f;
            w_s[ah][jl][ar] = wv;
            zpart += wv;
        }
        __syncthreads();

        // ---- phase B: acc[r] += w[r][h][j] * Wh[j, col], rows packed in pairs ----
        const float* whp = &g_Wh[(size_t)j0 * HID + col];
        #pragma unroll
        for (int jl = 0; jl < 32; jl++) {
            float whv = whp[jl * HID];
            unsigned long long wh2;
            asm("mov.b64 %0, {%1, %1};" : "=l"(wh2) : "r"(__float_as_uint(whv)));
            const unsigned long long* wp =
                (const unsigned long long*)&w_s[h][jl][0];
            #pragma unroll
            for (int rp = 0; rp < 8; rp++) {
                asm("fma.rn.f32x2 %0, %1, %2, %0;"
                    : "+l"(acc2[rp]) : "l"(wp[rp]), "l"(wh2));
            }
        }
        __syncthreads();
    }

    // ---- reduce Z (4 partials per (r,h)) ----
    zp[p][quarter] = zpart;
    __syncthreads();
    if (tid < 64)
        zfin[tid >> 2][tid & 3] = zp[tid][0] + zp[tid][1] + zp[tid][2] + zp[tid][3];
    __syncthreads();

    #pragma unroll
    for (int rp = 0; rp < 8; rp++) {
        float lo = __uint_as_float((unsigned)(acc2[rp] & 0xffffffffull));
        float hi = __uint_as_float((unsigned)(acc2[rp] >> 32));
        g_hn[(size_t)(row0 + 2 * rp)     * HID + col] = lo / zfin[2 * rp][h];
        g_hn[(size_t)(row0 + 2 * rp + 1) * HID + col] = hi / zfin[2 * rp + 1][h];
    }
}

// ---------------- residual combine: h = 0.5*relu(hn) + 0.5*h ----------------
__global__ void __launch_bounds__(256) combine_k()
{
    size_t i = (size_t)blockIdx.x * 256 + threadIdx.x;
    float hv = g_h[i], nv = g_hn[i];
    g_h[i] = 0.5f * fmaxf(nv, 0.f) + 0.5f * hv;
}

// ---------------- final scores + cosf ----------------
__global__ void __launch_bounds__(256) scorecos_k()
{
    __shared__ float q[HID];
    int tid = threadIdx.x;
    q[tid] = g_h[tid];
    __syncthreads();
    int w = tid >> 5, l = tid & 31;
    int j = blockIdx.x * 8 + w;
    if (j >= NS) return;
    const float* s = &g_h[(size_t)(S0 + j) * HID];
    float qs = 0.f, ss = 0.f;
    #pragma unroll
    for (int e = 0; e < 8; e++) {
        float x = s[l + 32 * e];
        qs += q[l + 32 * e] * x;
        ss += x * x;
    }
    qs = warpSum(qs);
    ss = warpSum(ss);
    if (l == 0) {
        g_scores[j] = qs * (1.0f / 16.0f);
        g_cosf[j] = qs * g_scal[1] / (sqrtf(ss) + 1e-8f);
    }
}

// ---------------- softmax over the 4063 scores (one CTA) ----------------
__global__ void __launch_bounds__(1024) softmax_k()
{
    __shared__ float sh[32];
    int tid = threadIdx.x, w = tid >> 5, l = tid & 31;

    float m = -1e30f;
    for (int i = tid; i < NS; i += 1024) m = fmaxf(m, g_scores[i]);
    m = warpMax(m);
    if (l == 0) sh[w] = m;
    __syncthreads();
    if (w == 0) {
        float mm = sh[l];
        mm = warpMax(mm);
        if (l == 0) sh[0] = mm;
    }
    __syncthreads();
    m = sh[0];
    __syncthreads();

    float sum = 0.f;
    for (int i = tid; i < NS; i += 1024) {
        float e = __expf(g_scores[i] - m);
        g_aw[i] = e;
        sum += e;
    }
    sum = warpSum(sum);
    if (l == 0) sh[w] = sum;
    __syncthreads();
    if (w == 0) {
        float ss = sh[l];
        ss = warpSum(ss);
        if (l == 0) sh[0] = ss;
    }
    __syncthreads();
    float inv = 1.f / sh[0];
    for (int i = tid; i < NS; i += 1024) g_aw[i] *= inv;
}

// ---------------- fusion MLP + output head ----------------
__global__ void __launch_bounds__(256) fusion_k(const float* __restrict__ fw,
                                                const float* __restrict__ fb,
                                                const float* __restrict__ ow,
                                                const float* __restrict__ obp,
                                                float* __restrict__ out)
{
    __shared__ float feat[514][16];   // [k][row]  (row-vectorized)
    __shared__ float awv[16], cosv[16];
    __shared__ float red2[16][8];
    int tid = threadIdx.x;
    int j0 = blockIdx.x * 16;

    if (tid < 16) {
        int j = j0 + tid;
        awv[tid]  = (j < NS) ? g_aw[j]   : 0.f;
        cosv[tid] = (j < NS) ? g_cosf[j] : 0.f;
    }
    __syncthreads();

    for (int idx = tid; idx < 16 * 514; idx += 256) {
        int r = idx / 514, k = idx - r * 514;
        int j = j0 + r;
        float v = 0.f;
        if (j < NS) {
            if (k < 256)      v = g_h[(size_t)(S0 + j) * HID + k];
            else if (k < 512) v = g_h[k - 256] * (awv[r] + 0.5f);
            else if (k == 512) v = cosv[r];
            else              v = awv[r];
        }
        feat[k][r] = v;
    }
    __syncthreads();

    int c = tid;
    float acc[16];
    #pragma unroll
    for (int r = 0; r < 16; r++) acc[r] = 0.f;
    const float* wrow = fw + (size_t)c * 514;
    for (int k = 0; k < 514; k++) {
        float wv = wrow[k];
        const float4* av = (const float4*)&feat[k][0];
        float4 a0 = av[0], a1 = av[1], a2 = av[2], a3 = av[3];
        acc[0]  += a0.x * wv; acc[1]  += a0.y * wv;
        acc[2]  += a0.z * wv; acc[3]  += a0.w * wv;
        acc[4]  += a1.x * wv; acc[5]  += a1.y * wv;
        acc[6]  += a1.z * wv; acc[7]  += a1.w * wv;
        acc[8]  += a2.x * wv; acc[9]  += a2.y * wv;
        acc[10] += a2.z * wv; acc[11] += a2.w * wv;
        acc[12] += a3.x * wv; acc[13] += a3.y * wv;
        acc[14] += a3.z * wv; acc[15] += a3.w * wv;
    }
    float fbv = fb[c];
    float owv = ow[c];
    int w = tid >> 5, l = tid & 31;
    #pragma unroll
    for (int r = 0; r < 16; r++) {
        float gv = fmaxf(acc[r] + fbv, 0.f) * owv;
        gv = warpSum(gv);
        if (l == 0) red2[r][w] = gv;
    }
    __syncthreads();
    if (tid < 16) {
        float s = 0.f;
        #pragma unroll
        for (int ww = 0; ww < 8; ww++) s += red2[tid][ww];
        int j = j0 + tid;
        if (j < NS) out[j] = s + obp[0] + 0.5f * cosv[tid];
    }
}

// ---------------- launch ----------------
extern "C" void kernel_launch(void* const* d_in, const int* in_sizes, int n_in,
                              void* d_out, int out_size)
{
    const float* emb    = (const float*)d_in[0];
    const int*   adj    = (const int*)  d_in[1];
    const float* proj_w = (const float*)d_in[3];
    const float* proj_b = (const float*)d_in[4];
    const float* ln_s   = (const float*)d_in[5];
    const float* ln_b   = (const float*)d_in[6];
    const float* gat_W  = (const float*)d_in[7];
    const float* gat_a  = (const float*)d_in[8];
    const float* fw     = (const float*)d_in[9];
    const float* fb     = (const float*)d_in[10];
    const float* ow     = (const float*)d_in[11];
    const float* ob     = (const float*)d_in[12];
    float* out = (float*)d_out;

    float *hP, *xP, *whP;
    cudaGetSymbolAddress((void**)&hP,  g_h);
    cudaGetSymbolAddress((void**)&xP,  g_x);
    cudaGetSymbolAddress((void**)&whP, g_Wh);

    // h = relu(E @ proj_w^T + b)
    gemm16<<<T_N / 16, 256>>>(emb, proj_w, proj_b, hP, EMB, 1);
    // query-aware cosine update of sentence rows
    rownorm0<<<1, 256>>>(0);
    cos_update<<<(NS + 7) / 8, 256>>>();

    for (int L = 0; L < 2; L++) {
        ln_k<<<T_N, 256>>>(ln_s + L * HID, ln_b + L * HID);
        gemm16<<<T_N / 16, 256>>>(xP, gat_W + (size_t)L * HID * HID, nullptr, whP, HID, 0);
        srcdst_k<<<T_N * NH / 8, 256>>>(gat_a + L * NH * 2 * HD);
        dmax_k<<<NH, 256>>>();
        attn_k<<<T_N / 16, 256>>>(adj);
        combine_k<<<T_N * HID / 256, 256>>>();
    }

    rownorm0<<<1, 256>>>(1);
    scorecos_k<<<(NS + 7) / 8, 256>>>();
    softmax_k<<<1, 1024>>>();
    fusion_k<<<(NS + 15) / 16, 256>>>(fw, fb, ow, ob, out);
}